// round 3
// baseline (speedup 1.0000x reference)
#include <cuda_runtime.h>
#include <math.h>

#define B_ 256
#define H_ 1024
#define P_ 3
#define S_ 512
#define EPSBN 1e-5f

// ---------------- static device scratch ----------------
__device__ float g_Wp[3 * H_ * H_];        // Wih[:, 3:1027] packed, K=1024
__device__ float g_gp[B_ * 3 * H_];        // palette @ Wih[:, :3]^T
__device__ float g_gi[B_ * 3 * H_];
__device__ float g_gh[B_ * 3 * H_];
__device__ float g_hc[B_ * 2 * H_];        // [h | context], rows of 2048
__device__ float g_qp[4 * B_ * H_];        // q split-K partials
__device__ float g_yp[4 * B_ * H_];        // y split-K partials
__device__ float g_y[B_ * H_];
__device__ float g_mu[H_];
__device__ float g_rstd[H_];
__device__ float g_pm[B_ * 4];
__device__ float g_pl[B_ * 4];
__device__ float g_pacc[B_ * 4 * H_];
__device__ float g_e[B_ * S_];

// =====================================================================
// GEMM core: 64x64 tile, 128 threads, 8x4 per thread, double-buffered.
// C[bm0..+64, bn0..+64] = A[M,K](lda) @ W[N,K](ldw)^T  (no bias)
// nt = K/16 tiles. All row pointers must be 16B aligned, K%16==0.
// =====================================================================
#define BM 64
#define BN 64
#define BK 16

__device__ __forceinline__ void gemm_core(
    const float* __restrict__ A, int lda,
    const float* __restrict__ W, int ldw,
    float* __restrict__ C, int ldc,
    int nt, int bm0, int bn0)
{
    __shared__ __align__(16) float As[2][BK][BM];
    __shared__ __align__(16) float Bs[2][BK][BN];

    const int tid = threadIdx.x;        // 0..127
    const int txn = tid & 15;           // n group (4 cols)
    const int tym = tid >> 4;           // m group (8 rows)

    const int r0 = tid >> 2;            // 0..31
    const int kc = (tid & 3) << 2;      // 0,4,8,12

    const float* Ar0 = A + (size_t)(bm0 + r0) * lda + kc;
    const float* Ar1 = A + (size_t)(bm0 + r0 + 32) * lda + kc;
    const float* Wr0 = W + (size_t)(bn0 + r0) * ldw + kc;
    const float* Wr1 = W + (size_t)(bn0 + r0 + 32) * ldw + kc;

    float4 pa0 = *(const float4*)Ar0;
    float4 pa1 = *(const float4*)Ar1;
    float4 pb0 = *(const float4*)Wr0;
    float4 pb1 = *(const float4*)Wr1;

    As[0][kc + 0][r0] = pa0.x; As[0][kc + 1][r0] = pa0.y;
    As[0][kc + 2][r0] = pa0.z; As[0][kc + 3][r0] = pa0.w;
    As[0][kc + 0][32 + r0] = pa1.x; As[0][kc + 1][32 + r0] = pa1.y;
    As[0][kc + 2][32 + r0] = pa1.z; As[0][kc + 3][32 + r0] = pa1.w;
    Bs[0][kc + 0][r0] = pb0.x; Bs[0][kc + 1][r0] = pb0.y;
    Bs[0][kc + 2][r0] = pb0.z; Bs[0][kc + 3][r0] = pb0.w;
    Bs[0][kc + 0][32 + r0] = pb1.x; Bs[0][kc + 1][32 + r0] = pb1.y;
    Bs[0][kc + 2][32 + r0] = pb1.z; Bs[0][kc + 3][32 + r0] = pb1.w;
    __syncthreads();

    float4 acc[8];
#pragma unroll
    for (int i = 0; i < 8; i++) acc[i] = make_float4(0.f, 0.f, 0.f, 0.f);

    for (int t = 0; t < nt; t++) {
        const int cur = t & 1;
        if (t + 1 < nt) {
            const int ko = (t + 1) * BK;
            pa0 = *(const float4*)(Ar0 + ko);
            pa1 = *(const float4*)(Ar1 + ko);
            pb0 = *(const float4*)(Wr0 + ko);
            pb1 = *(const float4*)(Wr1 + ko);
        }
#pragma unroll
        for (int kk = 0; kk < BK; kk++) {
            float4 av0 = *(const float4*)&As[cur][kk][tym << 3];
            float4 av1 = *(const float4*)&As[cur][kk][(tym << 3) + 4];
            float4 bv  = *(const float4*)&Bs[cur][kk][txn << 2];
            acc[0].x += av0.x * bv.x; acc[0].y += av0.x * bv.y; acc[0].z += av0.x * bv.z; acc[0].w += av0.x * bv.w;
            acc[1].x += av0.y * bv.x; acc[1].y += av0.y * bv.y; acc[1].z += av0.y * bv.z; acc[1].w += av0.y * bv.w;
            acc[2].x += av0.z * bv.x; acc[2].y += av0.z * bv.y; acc[2].z += av0.z * bv.z; acc[2].w += av0.z * bv.w;
            acc[3].x += av0.w * bv.x; acc[3].y += av0.w * bv.y; acc[3].z += av0.w * bv.z; acc[3].w += av0.w * bv.w;
            acc[4].x += av1.x * bv.x; acc[4].y += av1.x * bv.y; acc[4].z += av1.x * bv.z; acc[4].w += av1.x * bv.w;
            acc[5].x += av1.y * bv.x; acc[5].y += av1.y * bv.y; acc[5].z += av1.y * bv.z; acc[5].w += av1.y * bv.w;
            acc[6].x += av1.z * bv.x; acc[6].y += av1.z * bv.y; acc[6].z += av1.z * bv.z; acc[6].w += av1.z * bv.w;
            acc[7].x += av1.w * bv.x; acc[7].y += av1.w * bv.y; acc[7].z += av1.w * bv.z; acc[7].w += av1.w * bv.w;
        }
        if (t + 1 < nt) {
            const int nx = cur ^ 1;
            As[nx][kc + 0][r0] = pa0.x; As[nx][kc + 1][r0] = pa0.y;
            As[nx][kc + 2][r0] = pa0.z; As[nx][kc + 3][r0] = pa0.w;
            As[nx][kc + 0][32 + r0] = pa1.x; As[nx][kc + 1][32 + r0] = pa1.y;
            As[nx][kc + 2][32 + r0] = pa1.z; As[nx][kc + 3][32 + r0] = pa1.w;
            Bs[nx][kc + 0][r0] = pb0.x; Bs[nx][kc + 1][r0] = pb0.y;
            Bs[nx][kc + 2][r0] = pb0.z; Bs[nx][kc + 3][r0] = pb0.w;
            Bs[nx][kc + 0][32 + r0] = pb1.x; Bs[nx][kc + 1][32 + r0] = pb1.y;
            Bs[nx][kc + 2][32 + r0] = pb1.z; Bs[nx][kc + 3][32 + r0] = pb1.w;
            __syncthreads();
        }
    }

    const int m0 = bm0 + (tym << 3);
    const int n0 = bn0 + (txn << 2);
#pragma unroll
    for (int i = 0; i < 8; i++)
        *(float4*)&C[(size_t)(m0 + i) * ldc + n0] = acc[i];
}

// gi (z=0) and gh (z=1), identical shape: [256 x 3072], K=1024
__global__ void __launch_bounds__(128) gemm_dual(
    const float* __restrict__ ctx, const float* __restrict__ h0,
    const float* __restrict__ Whh)
{
    const float *A, *W;
    float *C;
    if (blockIdx.z == 0) { A = ctx; W = g_Wp; C = g_gi; }
    else                 { A = h0;  W = Whh;  C = g_gh; }
    gemm_core(A, H_, W, H_, C, 3 * H_, H_ / BK,
              blockIdx.y * BM, blockIdx.x * BN);
}

// split-K GEMM: blockIdx.z selects K chunk; partial C per chunk.
__global__ void __launch_bounds__(128) gemm_sk(
    const float* __restrict__ A, int lda,
    const float* __restrict__ W, int ldw,
    float* __restrict__ Cpart, int ldc, int kchunk)
{
    const int z = blockIdx.z;
    gemm_core(A + z * kchunk, lda, W + z * kchunk, ldw,
              Cpart + (size_t)z * B_ * ldc, ldc, kchunk / BK,
              blockIdx.y * BM, blockIdx.x * BN);
}

// =====================================================================
// pack Wih[:, 3:1027] -> g_Wp (K=1024)
// =====================================================================
__global__ void pack_w_kernel(const float* __restrict__ Wih)
{
    int idx = blockIdx.x * 256 + threadIdx.x;   // 3H * H
    int n = idx >> 10, k = idx & (H_ - 1);
    g_Wp[idx] = Wih[(size_t)n * (H_ + P_) + 3 + k];
}

// gp[b][n] = palette[b] . Wih[n][0:3]
__global__ void gp_kernel(const float* __restrict__ palette,
                          const float* __restrict__ Wih)
{
    __shared__ float w0[256], w1[256], w2[256];
    int n = blockIdx.x * 256 + threadIdx.x;     // 12 blocks
    w0[threadIdx.x] = Wih[(size_t)n * (H_ + P_) + 0];
    w1[threadIdx.x] = Wih[(size_t)n * (H_ + P_) + 1];
    w2[threadIdx.x] = Wih[(size_t)n * (H_ + P_) + 2];
    __syncthreads();
    for (int b = 0; b < B_; b++) {
        float p0 = palette[b * 3 + 0], p1 = palette[b * 3 + 1], p2 = palette[b * 3 + 2];
        g_gp[(size_t)b * 3 * H_ + n] =
            p0 * w0[threadIdx.x] + p1 * w1[threadIdx.x] + p2 * w2[threadIdx.x];
    }
}

// =====================================================================
// GRU gates: h = (1-z)*n + z*h0  -> g_hc[:, :H] and out_h
// =====================================================================
__global__ void gru_gate_kernel(const float* __restrict__ h0,
                                const float* __restrict__ bih,
                                const float* __restrict__ bhh,
                                float* __restrict__ out_h)
{
    int idx = blockIdx.x * 256 + threadIdx.x;
    int b = idx >> 10;
    int j = idx & (H_ - 1);
    size_t base = (size_t)b * (3 * H_);
    float gir = g_gi[base + j]          + g_gp[base + j]          + bih[j];
    float giz = g_gi[base + H_ + j]     + g_gp[base + H_ + j]     + bih[H_ + j];
    float gin = g_gi[base + 2 * H_ + j] + g_gp[base + 2 * H_ + j] + bih[2 * H_ + j];
    float ghr = g_gh[base + j]          + bhh[j];
    float ghz = g_gh[base + H_ + j]     + bhh[H_ + j];
    float ghn = g_gh[base + 2 * H_ + j] + bhh[2 * H_ + j];
    float r = 1.f / (1.f + __expf(-(gir + ghr)));
    float z = 1.f / (1.f + __expf(-(giz + ghz)));
    float n = tanhf(gin + r * ghn);
    float h = (1.f - z) * n + z * h0[idx];
    g_hc[(size_t)b * (2 * H_) + j] = h;
    if (out_h) out_h[idx] = h;
}

// =====================================================================
// Attention, 4 seq partitions per batch row. Assembles q from split-K
// partials + bias, L2-normalizes, online softmax.
// =====================================================================
__global__ void attn_part_kernel(const float* __restrict__ enc,
                                 const int* __restrict__ lens,
                                 const float* __restrict__ attn_b)
{
    const int b = blockIdx.x;
    const int p = blockIdx.y;
    const int tid = threadIdx.x;
    const int warp = tid >> 5, lane = tid & 31;

    __shared__ __align__(16) float q_s[H_];
    __shared__ __align__(16) float tile[8][H_];
    __shared__ float e_chunk[8];
    __shared__ float red[8];

    float qv[4];
    float ss = 0.f;
#pragma unroll
    for (int c = 0; c < 4; c++) {
        int h = tid + 256 * c;
        float q = attn_b[h];
#pragma unroll
        for (int pp = 0; pp < 4; pp++)
            q += g_qp[(size_t)pp * B_ * H_ + (size_t)b * H_ + h];
        qv[c] = q;
        ss += q * q;
    }
#pragma unroll
    for (int o = 16; o; o >>= 1) ss += __shfl_xor_sync(0xffffffffu, ss, o);
    if (lane == 0) red[warp] = ss;
    __syncthreads();
    float tot = red[0] + red[1] + red[2] + red[3] + red[4] + red[5] + red[6] + red[7];
    float qinv = rsqrtf(tot);
#pragma unroll
    for (int c = 0; c < 4; c++) q_s[tid + 256 * c] = qv[c] * qinv;
    __syncthreads();

    const int len = lens[b];
    const int sb = p * (S_ / 4);
    const int se = min(len, sb + (S_ / 4));

    float m = -INFINITY, l = 0.f;
    float acc[4] = {0.f, 0.f, 0.f, 0.f};

    for (int s0 = sb; s0 < se; s0 += 8) {
        int rows = min(8, se - s0);
#pragma unroll
        for (int j = 0; j < 8; j++) {
            if (j < rows) {
                const float4* src = (const float4*)(enc + (((size_t)(s0 + j)) * B_ + b) * H_);
                ((float4*)tile[j])[tid] = src[tid];
            } else {
                ((float4*)tile[j])[tid] = make_float4(0.f, 0.f, 0.f, 0.f);
            }
        }
        __syncthreads();
        if (warp < rows) {
            const float4* trow = (const float4*)tile[warp];
            const float4* qrow = (const float4*)q_s;
            float e = 0.f;
#pragma unroll
            for (int j = 0; j < 8; j++) {
                float4 t = trow[lane + 32 * j];
                float4 q4 = qrow[lane + 32 * j];
                e += t.x * q4.x + t.y * q4.y + t.z * q4.z + t.w * q4.w;
            }
#pragma unroll
            for (int o = 16; o; o >>= 1) e += __shfl_xor_sync(0xffffffffu, e, o);
            if (lane == 0) e_chunk[warp] = e;
        }
        __syncthreads();
        float cm = -INFINITY;
        for (int i = 0; i < rows; i++) cm = fmaxf(cm, e_chunk[i]);
        float m_new = fmaxf(m, cm);
        float scale = (m == -INFINITY) ? 0.f : __expf(m - m_new);
        float pr[8];
        float lsum = 0.f;
#pragma unroll
        for (int i = 0; i < 8; i++) {
            pr[i] = (i < rows) ? __expf(e_chunk[i] - m_new) : 0.f;
            lsum += pr[i];
        }
        l = l * scale + lsum;
#pragma unroll
        for (int c = 0; c < 4; c++) {
            float a = acc[c] * scale;
#pragma unroll
            for (int i = 0; i < 8; i++) a += pr[i] * tile[i][tid + 256 * c];
            acc[c] = a;
        }
        m = m_new;
        if (tid < rows) g_e[(size_t)b * S_ + s0 + tid] = e_chunk[tid];
        __syncthreads();
    }

    if (tid == 0) { g_pm[b * 4 + p] = m; g_pl[b * 4 + p] = l; }
#pragma unroll
    for (int c = 0; c < 4; c++)
        g_pacc[((size_t)(b * 4 + p)) * H_ + tid + 256 * c] = acc[c];
}

__global__ void attn_comb_kernel(const int* __restrict__ lens,
                                 float* __restrict__ out_ctx,
                                 float* __restrict__ out_w)
{
    const int b = blockIdx.x;
    const int tid = threadIdx.x;

    float mp[4], lp[4];
#pragma unroll
    for (int p = 0; p < 4; p++) { mp[p] = g_pm[b * 4 + p]; lp[p] = g_pl[b * 4 + p]; }
    float m = fmaxf(fmaxf(mp[0], mp[1]), fmaxf(mp[2], mp[3]));
    float sc[4];
    float l = 0.f;
#pragma unroll
    for (int p = 0; p < 4; p++) {
        sc[p] = (lp[p] > 0.f) ? __expf(mp[p] - m) : 0.f;
        l += lp[p] * sc[p];
    }
    float invl = 1.f / l;

#pragma unroll
    for (int c = 0; c < 4; c++) {
        int h = tid + 256 * c;
        float v = 0.f;
#pragma unroll
        for (int p = 0; p < 4; p++)
            v += g_pacc[((size_t)(b * 4 + p)) * H_ + h] * sc[p];
        v *= invl;
        g_hc[(size_t)b * (2 * H_) + H_ + h] = v;
        if (out_ctx) out_ctx[(size_t)b * H_ + h] = v;
    }

    if (out_w) {
        int len = lens[b];
        for (int s = tid; s < S_; s += 256) {
            float w = (s < len) ? __expf(g_e[(size_t)b * S_ + s] - m) * invl : 0.f;
            out_w[(size_t)b * S_ + s] = w;
        }
    }
}

// =====================================================================
// fused: sum y split-K partials + bias + ReLU -> g_y, and BN stats
// =====================================================================
__global__ void bn_reduce_stats(const float* __restrict__ b1)
{
    int h = blockIdx.x * 256 + threadIdx.x;
    float bias = b1[h];
    float s = 0.f, s2 = 0.f;
    for (int b = 0; b < B_; b++) {
        size_t o = (size_t)b * H_ + h;
        float v = g_yp[o] + g_yp[(size_t)B_ * H_ + o]
                + g_yp[2 * (size_t)B_ * H_ + o] + g_yp[3 * (size_t)B_ * H_ + o] + bias;
        v = fmaxf(v, 0.f);
        g_y[o] = v;
        s += v;
        s2 += v * v;
    }
    float mu = s * (1.f / B_);
    float var = fmaxf(s2 * (1.f / B_) - mu * mu, 0.f);
    g_mu[h] = mu;
    g_rstd[h] = rsqrtf(var + EPSBN);
}

__global__ void out_kernel(const float* __restrict__ gamma,
                           const float* __restrict__ beta,
                           const float* __restrict__ W2,
                           const float* __restrict__ b2,
                           float* __restrict__ out)
{
    int b = blockIdx.x, tid = threadIdx.x;
    int warp = tid >> 5, lane = tid & 31;
    __shared__ float red[3][8];
    float s0 = 0.f, s1 = 0.f, s2 = 0.f;
#pragma unroll
    for (int c = 0; c < 4; c++) {
        int hh = tid + 256 * c;
        float y = g_y[(size_t)b * H_ + hh];
        float yn = (y - g_mu[hh]) * g_rstd[hh] * gamma[hh] + beta[hh];
        s0 += yn * W2[hh];
        s1 += yn * W2[H_ + hh];
        s2 += yn * W2[2 * H_ + hh];
    }
#pragma unroll
    for (int o = 16; o; o >>= 1) {
        s0 += __shfl_xor_sync(0xffffffffu, s0, o);
        s1 += __shfl_xor_sync(0xffffffffu, s1, o);
        s2 += __shfl_xor_sync(0xffffffffu, s2, o);
    }
    if (lane == 0) { red[0][warp] = s0; red[1][warp] = s1; red[2][warp] = s2; }
    __syncthreads();
    if (tid < 3) {
        float t = 0.f;
#pragma unroll
        for (int w = 0; w < 8; w++) t += red[tid][w];
        out[b * 3 + tid] = t + b2[tid];
    }
}

// =====================================================================
// launcher
// =====================================================================
extern "C" void kernel_launch(void* const* d_in, const int* in_sizes, int n_in,
                              void* d_out, int out_size)
{
    const float* palette  = (const float*)d_in[0];
    const float* last_ctx = (const float*)d_in[1];
    const float* last_h   = (const float*)d_in[2];
    const float* enc      = (const float*)d_in[3];
    const int*   lens     = (const int*)d_in[4];
    const float* attn_W = (const float*)d_in[6];
    const float* attn_b = (const float*)d_in[7];
    const float* Wih    = (const float*)d_in[8];
    const float* Whh    = (const float*)d_in[9];
    const float* bih    = (const float*)d_in[10];
    const float* bhh    = (const float*)d_in[11];
    const float* W1     = (const float*)d_in[12];
    const float* b1     = (const float*)d_in[13];
    const float* gamma  = (const float*)d_in[14];
    const float* beta   = (const float*)d_in[15];
    const float* W2     = (const float*)d_in[16];
    const float* b2     = (const float*)d_in[17];

    float* out_main = (float*)d_out;
    float* out_ctx = 0;
    float* out_h = 0;
    float* out_w = 0;
    if (out_size >= B_ * 3 + 2 * B_ * H_ + B_ * S_) {
        out_ctx = out_main + B_ * 3;
        out_h   = out_ctx + B_ * H_;
        out_w   = out_h + B_ * H_;
    }

    float *p_hc, *p_qp, *p_yp;
    cudaGetSymbolAddress((void**)&p_hc, g_hc);
    cudaGetSymbolAddress((void**)&p_qp, g_qp);
    cudaGetSymbolAddress((void**)&p_yp, g_yp);

    // 0) pack Wih (strip palette cols), palette partial product
    pack_w_kernel<<<(3 * H_ * H_) / 256, 256>>>(Wih);
    gp_kernel<<<(3 * H_) / 256, 256>>>(palette, Wih);

    // 1) gi = ctx @ Wp^T, gh = h0 @ Whh^T  (384 blocks)
    gemm_dual<<<dim3(3 * H_ / BN, B_ / BM, 2), 128>>>(last_ctx, last_h, Whh);

    // 2) gates -> h
    gru_gate_kernel<<<(B_ * H_) / 256, 256>>>(last_h, bih, bhh, out_h);

    // 3) q partials = h @ attn_W^T (split-K 4, 256 blocks)
    gemm_sk<<<dim3(H_ / BN, B_ / BM, 4), 128>>>(
        p_hc, 2 * H_, attn_W, H_, p_qp, H_, H_ / 4);

    // 4) attention
    attn_part_kernel<<<dim3(B_, 4), 256>>>(enc, lens, attn_b);
    attn_comb_kernel<<<B_, 256>>>(lens, out_ctx, out_w);

    // 5) y partials = [h|ctx] @ W1^T (split-K 4, 256 blocks)
    gemm_sk<<<dim3(H_ / BN, B_ / BM, 4), 128>>>(
        p_hc, 2 * H_, W1, 2 * H_, p_yp, H_, 2 * H_ / 4);

    // 6) y reduce + ReLU + BN stats, then final projection
    bn_reduce_stats<<<H_ / 256, 256>>>(b1);
    out_kernel<<<B_, 256>>>(gamma, beta, W2, b2, out_main);
}

// round 5
// speedup vs baseline: 1.2549x; 1.2549x over previous
#include <cuda_runtime.h>
#include <cuda_bf16.h>
#include <math.h>
#include <cstdint>

#define B_ 256
#define H_ 1024
#define P_ 3
#define S_ 512
#define EPSBN 1e-5f

// ---------------- static device scratch ----------------
__device__ __align__(16) __nv_bfloat16 g_wih_hi[3 * H_ * H_];
__device__ __align__(16) __nv_bfloat16 g_wih_lo[3 * H_ * H_];
__device__ __align__(16) __nv_bfloat16 g_whh_hi[3 * H_ * H_];
__device__ __align__(16) __nv_bfloat16 g_whh_lo[3 * H_ * H_];
__device__ __align__(16) __nv_bfloat16 g_qw_hi[H_ * H_];
__device__ __align__(16) __nv_bfloat16 g_qw_lo[H_ * H_];
__device__ __align__(16) __nv_bfloat16 g_w1_hi[H_ * 2 * H_];
__device__ __align__(16) __nv_bfloat16 g_w1_lo[H_ * 2 * H_];
__device__ __align__(16) __nv_bfloat16 g_xc_hi[B_ * H_];
__device__ __align__(16) __nv_bfloat16 g_xc_lo[B_ * H_];
__device__ __align__(16) __nv_bfloat16 g_xh_hi[B_ * H_];
__device__ __align__(16) __nv_bfloat16 g_xh_lo[B_ * H_];
__device__ __align__(16) __nv_bfloat16 g_hc_hi[B_ * 2 * H_];
__device__ __align__(16) __nv_bfloat16 g_hc_lo[B_ * 2 * H_];

__device__ float g_gp[B_ * 3 * H_];
__device__ float g_gi[B_ * 3 * H_];
__device__ float g_gh[B_ * 3 * H_];
__device__ float g_qp[2 * B_ * H_];
__device__ float g_yp[2 * B_ * H_];
__device__ float g_y[B_ * H_];
__device__ float g_mu[H_];
__device__ float g_rstd[H_];
__device__ float g_pm[B_ * 4];
__device__ float g_pl[B_ * 4];
__device__ float g_pacc[B_ * 4 * H_];
__device__ float g_e[B_ * S_];

// =====================================================================
// helpers
// =====================================================================
__device__ __forceinline__ void split1(float x, __nv_bfloat16& h, __nv_bfloat16& l)
{
    h = __float2bfloat16(x);
    l = __float2bfloat16(x - __bfloat162float(h));
}

__device__ __forceinline__ uint32_t smem_u32(const void* p)
{
    uint32_t a;
    asm("{ .reg .u64 t; cvta.to.shared.u64 t, %1; cvt.u32.u64 %0, t; }"
        : "=r"(a) : "l"(p));
    return a;
}

__device__ __forceinline__ void ldsm_x4(uint32_t* r, uint32_t addr)
{
    asm volatile("ldmatrix.sync.aligned.m8n8.x4.shared.b16 {%0,%1,%2,%3}, [%4];"
        : "=r"(r[0]), "=r"(r[1]), "=r"(r[2]), "=r"(r[3]) : "r"(addr));
}

__device__ __forceinline__ void mma_bf16(float* d, const uint32_t* a, const uint32_t* b)
{
    asm volatile(
        "mma.sync.aligned.m16n8k16.row.col.f32.bf16.bf16.f32 "
        "{%0,%1,%2,%3}, {%4,%5,%6,%7}, {%8,%9}, {%0,%1,%2,%3};"
        : "+f"(d[0]), "+f"(d[1]), "+f"(d[2]), "+f"(d[3])
        : "r"(a[0]), "r"(a[1]), "r"(a[2]), "r"(a[3]), "r"(b[0]), "r"(b[1]));
}

// =====================================================================
// mma GEMM core: 64x64 C tile per CTA, 4 warps (each 32x32), BK=32,
// double-buffered smem. A[M,K] bf16 hi/lo (lda), B = W[N,K] bf16 hi/lo
// (ldb), C fp32 (ldc). K consumed = nchunks*32.
// smem region layout: 8 regions of 64*40 bf16 (5120 B):
//   region(buf, m): buf*4 + m, m: 0=Ahi 1=Alo 2=Bhi 3=Blo
// =====================================================================
#define RSZ 5120
#define RST 40   // smem row stride in bf16

__device__ void mma_core(
    const __nv_bfloat16* __restrict__ Ahi, const __nv_bfloat16* __restrict__ Alo, int lda,
    const __nv_bfloat16* __restrict__ Bhi, const __nv_bfloat16* __restrict__ Blo, int ldb,
    float* __restrict__ C, int ldc,
    int nchunks, int bm0, int bn0)
{
    __shared__ __align__(16) unsigned char sm[8 * RSZ];
    const uint32_t sb = smem_u32(sm);

    const int tid = threadIdx.x;           // 0..127
    const int wid = tid >> 5, lane = tid & 31;
    const int wm = (wid >> 1) * 32;        // warp row offset in tile
    const int wn = (wid & 1) * 32;         // warp col offset in tile

    // per-thread staging coords (2 x 16B per matrix per chunk)
    const int e0 = tid, e1 = 128 + tid;
    const int r0 = e0 >> 2, c0 = (e0 & 3) * 8;
    const int r1 = e1 >> 2, c1 = (e1 & 3) * 8;

    const __nv_bfloat16* Ah0 = Ahi + (size_t)(bm0 + r0) * lda + c0;
    const __nv_bfloat16* Ah1 = Ahi + (size_t)(bm0 + r1) * lda + c1;
    const __nv_bfloat16* Al0 = Alo + (size_t)(bm0 + r0) * lda + c0;
    const __nv_bfloat16* Al1 = Alo + (size_t)(bm0 + r1) * lda + c1;
    const __nv_bfloat16* Bh0 = Bhi + (size_t)(bn0 + r0) * ldb + c0;
    const __nv_bfloat16* Bh1 = Bhi + (size_t)(bn0 + r1) * ldb + c1;
    const __nv_bfloat16* Bl0 = Blo + (size_t)(bn0 + r0) * ldb + c0;
    const __nv_bfloat16* Bl1 = Blo + (size_t)(bn0 + r1) * ldb + c1;

    const uint32_t so0 = (uint32_t)(r0 * RST + c0) * 2;
    const uint32_t so1 = (uint32_t)(r1 * RST + c1) * 2;

    uint4 pre[8];
#define LOADCH(kb) do { \
        pre[0] = *(const uint4*)(Ah0 + (kb)); pre[1] = *(const uint4*)(Ah1 + (kb)); \
        pre[2] = *(const uint4*)(Al0 + (kb)); pre[3] = *(const uint4*)(Al1 + (kb)); \
        pre[4] = *(const uint4*)(Bh0 + (kb)); pre[5] = *(const uint4*)(Bh1 + (kb)); \
        pre[6] = *(const uint4*)(Bl0 + (kb)); pre[7] = *(const uint4*)(Bl1 + (kb)); \
    } while (0)

#define STORECH(buf) do { \
        unsigned char* base = sm + (buf) * 4 * RSZ; \
        *(uint4*)(base + so0)            = pre[0]; *(uint4*)(base + so1)            = pre[1]; \
        *(uint4*)(base + RSZ + so0)      = pre[2]; *(uint4*)(base + RSZ + so1)      = pre[3]; \
        *(uint4*)(base + 2 * RSZ + so0)  = pre[4]; *(uint4*)(base + 2 * RSZ + so1)  = pre[5]; \
        *(uint4*)(base + 3 * RSZ + so0)  = pre[6]; *(uint4*)(base + 3 * RSZ + so1)  = pre[7]; \
    } while (0)

    float acc[2][4][4];
#pragma unroll
    for (int i = 0; i < 2; i++)
#pragma unroll
        for (int j = 0; j < 4; j++)
#pragma unroll
            for (int k = 0; k < 4; k++) acc[i][j][k] = 0.f;

    // ldmatrix per-lane offsets (within a region)
    const uint32_t a_off = (uint32_t)(((wm + (lane & 15)) * RST + (lane >> 4) * 8) * 2);
    const uint32_t b_off = (uint32_t)(((wn + ((lane >> 4) << 3) + (lane & 7)) * RST
                                       + ((lane >> 3) & 1) * 8) * 2);

    LOADCH(0);
    STORECH(0);
    __syncthreads();

    for (int t = 0; t < nchunks; t++) {
        const int buf = t & 1;
        if (t + 1 < nchunks) LOADCH((t + 1) * 32);

        const uint32_t aHi = sb + buf * 4 * RSZ;
        const uint32_t aLo = aHi + RSZ;
        const uint32_t bHi = aHi + 2 * RSZ;
        const uint32_t bLo = aHi + 3 * RSZ;

#pragma unroll
        for (int kt = 0; kt < 2; kt++) {
            const uint32_t ko = (uint32_t)(kt * 16 * 2);
            uint32_t ah0[4], ah1[4], al0[4], al1[4];
            ldsm_x4(ah0, aHi + a_off + ko);
            ldsm_x4(ah1, aHi + a_off + ko + 16 * RST * 2);
            ldsm_x4(al0, aLo + a_off + ko);
            ldsm_x4(al1, aLo + a_off + ko + 16 * RST * 2);
            uint32_t bh0[4], bh1[4], bl0[4], bl1[4];
            ldsm_x4(bh0, bHi + b_off + ko);
            ldsm_x4(bh1, bHi + b_off + ko + 16 * RST * 2);
            ldsm_x4(bl0, bLo + b_off + ko);
            ldsm_x4(bl1, bLo + b_off + ko + 16 * RST * 2);

#pragma unroll
            for (int mt = 0; mt < 2; mt++) {
                const uint32_t* AH = mt ? ah1 : ah0;
                const uint32_t* AL = mt ? al1 : al0;
#pragma unroll
                for (int nn = 0; nn < 4; nn++) {
                    const uint32_t* BH = ((nn < 2) ? bh0 : bh1) + (nn & 1) * 2;
                    const uint32_t* BL = ((nn < 2) ? bl0 : bl1) + (nn & 1) * 2;
                    float* d = acc[mt][nn];
                    mma_bf16(d, AH, BH);
                    mma_bf16(d, AH, BL);
                    mma_bf16(d, AL, BH);
                }
            }
        }
        if (t + 1 < nchunks) {
            STORECH(buf ^ 1);
            __syncthreads();
        }
    }

    // epilogue
    const int er = lane >> 2;             // 0..7
    const int ec = (lane & 3) * 2;
#pragma unroll
    for (int mt = 0; mt < 2; mt++) {
#pragma unroll
        for (int nn = 0; nn < 4; nn++) {
            const int row = bm0 + wm + mt * 16 + er;
            const int col = bn0 + wn + nn * 8 + ec;
            float* d = acc[mt][nn];
            *(float2*)&C[(size_t)row * ldc + col]       = make_float2(d[0], d[1]);
            *(float2*)&C[(size_t)(row + 8) * ldc + col] = make_float2(d[2], d[3]);
        }
    }
#undef LOADCH
#undef STORECH
}

// gi (z=0): xc @ Wih'(K1024)^T;  gh (z=1): xh @ Whh^T.  N=3072.
__global__ void __launch_bounds__(128) gemm_dual()
{
    const int bm0 = blockIdx.y * 64, bn0 = blockIdx.x * 64;
    if (blockIdx.z == 0)
        mma_core(g_xc_hi, g_xc_lo, H_, g_wih_hi, g_wih_lo, H_,
                 g_gi, 3 * H_, 32, bm0, bn0);
    else
        mma_core(g_xh_hi, g_xh_lo, H_, g_whh_hi, g_whh_lo, H_,
                 g_gh, 3 * H_, 32, bm0, bn0);
}

// q partials: h(hc cols 0..1023) @ attn_W^T, split-K 2
__global__ void __launch_bounds__(128) gemm_q()
{
    const int z = blockIdx.z;
    mma_core(g_hc_hi + z * 512, g_hc_lo + z * 512, 2 * H_,
             g_qw_hi + z * 512, g_qw_lo + z * 512, H_,
             g_qp + (size_t)z * B_ * H_, H_, 16,
             blockIdx.y * 64, blockIdx.x * 64);
}

// y partials: [h|ctx](K=2048) @ W1^T, split-K 2
__global__ void __launch_bounds__(128) gemm_y()
{
    const int z = blockIdx.z;
    mma_core(g_hc_hi + z * 1024, g_hc_lo + z * 1024, 2 * H_,
             g_w1_hi + z * 1024, g_w1_lo + z * 1024, 2 * H_,
             g_yp + (size_t)z * B_ * H_, H_, 32,
             blockIdx.y * 64, blockIdx.x * 64);
}

// =====================================================================
// packing
// =====================================================================
__global__ void pack_w_kernel(const float* __restrict__ W, int ldw, int woff,
                              __nv_bfloat16* __restrict__ hi,
                              __nv_bfloat16* __restrict__ lo, int kshift)
{
    size_t idx = (size_t)blockIdx.x * 256 + threadIdx.x;
    int n = (int)(idx >> kshift);
    int k = (int)(idx & ((1u << kshift) - 1));
    float v = W[(size_t)n * ldw + woff + k];
    __nv_bfloat16 h, l;
    split1(v, h, l);
    hi[idx] = h;
    lo[idx] = l;
}

__global__ void pack_act_kernel(const float* __restrict__ ctx,
                                const float* __restrict__ h0)
{
    int idx = blockIdx.x * 256 + threadIdx.x;     // B*H
    __nv_bfloat16 h, l;
    split1(ctx[idx], h, l); g_xc_hi[idx] = h; g_xc_lo[idx] = l;
    split1(h0[idx],  h, l); g_xh_hi[idx] = h; g_xh_lo[idx] = l;
}

// gp[b][n] = palette[b] . Wih[n][0:3]
__global__ void gp_kernel(const float* __restrict__ palette,
                          const float* __restrict__ Wih)
{
    __shared__ float w0[256], w1[256], w2[256];
    int n = blockIdx.x * 256 + threadIdx.x;
    w0[threadIdx.x] = Wih[(size_t)n * (H_ + P_) + 0];
    w1[threadIdx.x] = Wih[(size_t)n * (H_ + P_) + 1];
    w2[threadIdx.x] = Wih[(size_t)n * (H_ + P_) + 2];
    __syncthreads();
    for (int b = 0; b < B_; b++) {
        float p0 = palette[b * 3 + 0], p1 = palette[b * 3 + 1], p2 = palette[b * 3 + 2];
        g_gp[(size_t)b * 3 * H_ + n] =
            p0 * w0[threadIdx.x] + p1 * w1[threadIdx.x] + p2 * w2[threadIdx.x];
    }
}

// =====================================================================
// GRU gates: h -> out_h + g_hc hi/lo [:, :H]
// =====================================================================
__global__ void gru_gate_kernel(const float* __restrict__ h0,
                                const float* __restrict__ bih,
                                const float* __restrict__ bhh,
                                float* __restrict__ out_h)
{
    int idx = blockIdx.x * 256 + threadIdx.x;
    int b = idx >> 10;
    int j = idx & (H_ - 1);
    size_t base = (size_t)b * (3 * H_);
    float gir = g_gi[base + j]          + g_gp[base + j]          + bih[j];
    float giz = g_gi[base + H_ + j]     + g_gp[base + H_ + j]     + bih[H_ + j];
    float gin = g_gi[base + 2 * H_ + j] + g_gp[base + 2 * H_ + j] + bih[2 * H_ + j];
    float ghr = g_gh[base + j]          + bhh[j];
    float ghz = g_gh[base + H_ + j]     + bhh[H_ + j];
    float ghn = g_gh[base + 2 * H_ + j] + bhh[2 * H_ + j];
    float r = 1.f / (1.f + __expf(-(gir + ghr)));
    float z = 1.f / (1.f + __expf(-(giz + ghz)));
    float n = tanhf(gin + r * ghn);
    float h = (1.f - z) * n + z * h0[idx];
    __nv_bfloat16 hh, hl;
    split1(h, hh, hl);
    size_t o = (size_t)b * (2 * H_) + j;
    g_hc_hi[o] = hh;
    g_hc_lo[o] = hl;
    if (out_h) out_h[idx] = h;
}

// =====================================================================
// Attention: 4 seq partitions per batch row; q = 2 partials + bias.
// =====================================================================
__global__ void attn_part_kernel(const float* __restrict__ enc,
                                 const int* __restrict__ lens,
                                 const float* __restrict__ attn_b)
{
    const int b = blockIdx.x;
    const int p = blockIdx.y;
    const int tid = threadIdx.x;
    const int warp = tid >> 5, lane = tid & 31;

    __shared__ __align__(16) float q_s[H_];
    __shared__ __align__(16) float tile[8][H_];
    __shared__ float e_chunk[8];
    __shared__ float red[8];

    float qv[4];
    float ss = 0.f;
#pragma unroll
    for (int c = 0; c < 4; c++) {
        int h = tid + 256 * c;
        size_t o = (size_t)b * H_ + h;
        float q = attn_b[h] + g_qp[o] + g_qp[(size_t)B_ * H_ + o];
        qv[c] = q;
        ss += q * q;
    }
#pragma unroll
    for (int o = 16; o; o >>= 1) ss += __shfl_xor_sync(0xffffffffu, ss, o);
    if (lane == 0) red[warp] = ss;
    __syncthreads();
    float tot = red[0] + red[1] + red[2] + red[3] + red[4] + red[5] + red[6] + red[7];
    float qinv = rsqrtf(tot);
#pragma unroll
    for (int c = 0; c < 4; c++) q_s[tid + 256 * c] = qv[c] * qinv;
    __syncthreads();

    const int len = lens[b];
    const int sb = p * (S_ / 4);
    const int se = min(len, sb + (S_ / 4));

    float m = -INFINITY, l = 0.f;
    float acc[4] = {0.f, 0.f, 0.f, 0.f};

    for (int s0 = sb; s0 < se; s0 += 8) {
        int rows = min(8, se - s0);
#pragma unroll
        for (int j = 0; j < 8; j++) {
            if (j < rows) {
                const float4* src = (const float4*)(enc + (((size_t)(s0 + j)) * B_ + b) * H_);
                ((float4*)tile[j])[tid] = src[tid];
            } else {
                ((float4*)tile[j])[tid] = make_float4(0.f, 0.f, 0.f, 0.f);
            }
        }
        __syncthreads();
        if (warp < rows) {
            const float4* trow = (const float4*)tile[warp];
            const float4* qrow = (const float4*)q_s;
            float e = 0.f;
#pragma unroll
            for (int j = 0; j < 8; j++) {
                float4 t = trow[lane + 32 * j];
                float4 q4 = qrow[lane + 32 * j];
                e += t.x * q4.x + t.y * q4.y + t.z * q4.z + t.w * q4.w;
            }
#pragma unroll
            for (int o = 16; o; o >>= 1) e += __shfl_xor_sync(0xffffffffu, e, o);
            if (lane == 0) e_chunk[warp] = e;
        }
        __syncthreads();
        float cm = -INFINITY;
        for (int i = 0; i < rows; i++) cm = fmaxf(cm, e_chunk[i]);
        float m_new = fmaxf(m, cm);
        float scale = (m == -INFINITY) ? 0.f : __expf(m - m_new);
        float pr[8];
        float lsum = 0.f;
#pragma unroll
        for (int i = 0; i < 8; i++) {
            pr[i] = (i < rows) ? __expf(e_chunk[i] - m_new) : 0.f;
            lsum += pr[i];
        }
        l = l * scale + lsum;
#pragma unroll
        for (int c = 0; c < 4; c++) {
            float a = acc[c] * scale;
#pragma unroll
            for (int i = 0; i < 8; i++) a += pr[i] * tile[i][tid + 256 * c];
            acc[c] = a;
        }
        m = m_new;
        if (tid < rows) g_e[(size_t)b * S_ + s0 + tid] = e_chunk[tid];
        __syncthreads();
    }

    if (tid == 0) { g_pm[b * 4 + p] = m; g_pl[b * 4 + p] = l; }
#pragma unroll
    for (int c = 0; c < 4; c++)
        g_pacc[((size_t)(b * 4 + p)) * H_ + tid + 256 * c] = acc[c];
}

__global__ void attn_comb_kernel(const int* __restrict__ lens,
                                 float* __restrict__ out_ctx,
                                 float* __restrict__ out_w)
{
    const int b = blockIdx.x;
    const int tid = threadIdx.x;

    float mp[4], lp[4];
#pragma unroll
    for (int p = 0; p < 4; p++) { mp[p] = g_pm[b * 4 + p]; lp[p] = g_pl[b * 4 + p]; }
    float m = fmaxf(fmaxf(mp[0], mp[1]), fmaxf(mp[2], mp[3]));
    float sc[4];
    float l = 0.f;
#pragma unroll
    for (int p = 0; p < 4; p++) {
        sc[p] = (lp[p] > 0.f) ? __expf(mp[p] - m) : 0.f;
        l += lp[p] * sc[p];
    }
    float invl = 1.f / l;

#pragma unroll
    for (int c = 0; c < 4; c++) {
        int h = tid + 256 * c;
        float v = 0.f;
#pragma unroll
        for (int p = 0; p < 4; p++)
            v += g_pacc[((size_t)(b * 4 + p)) * H_ + h] * sc[p];
        v *= invl;
        __nv_bfloat16 vh, vl;
        split1(v, vh, vl);
        size_t o = (size_t)b * (2 * H_) + H_ + h;
        g_hc_hi[o] = vh;
        g_hc_lo[o] = vl;
        if (out_ctx) out_ctx[(size_t)b * H_ + h] = v;
    }

    if (out_w) {
        int len = lens[b];
        for (int s = tid; s < S_; s += 256) {
            float w = (s < len) ? __expf(g_e[(size_t)b * S_ + s] - m) * invl : 0.f;
            out_w[(size_t)b * S_ + s] = w;
        }
    }
}

// =====================================================================
// y = relu(partials + bias); BN stats; final projection
// =====================================================================
__global__ void bn_reduce_stats(const float* __restrict__ b1)
{
    int h = blockIdx.x * 256 + threadIdx.x;
    float bias = b1[h];
    float s = 0.f, s2 = 0.f;
    for (int b = 0; b < B_; b++) {
        size_t o = (size_t)b * H_ + h;
        float v = g_yp[o] + g_yp[(size_t)B_ * H_ + o] + bias;
        v = fmaxf(v, 0.f);
        g_y[o] = v;
        s += v;
        s2 += v * v;
    }
    float mu = s * (1.f / B_);
    float var = fmaxf(s2 * (1.f / B_) - mu * mu, 0.f);
    g_mu[h] = mu;
    g_rstd[h] = rsqrtf(var + EPSBN);
}

__global__ void out_kernel(const float* __restrict__ gamma,
                           const float* __restrict__ beta,
                           const float* __restrict__ W2,
                           const float* __restrict__ b2,
                           float* __restrict__ out)
{
    int b = blockIdx.x, tid = threadIdx.x;
    int warp = tid >> 5, lane = tid & 31;
    __shared__ float red[3][8];
    float s0 = 0.f, s1 = 0.f, s2 = 0.f;
#pragma unroll
    for (int c = 0; c < 4; c++) {
        int hh = tid + 256 * c;
        float y = g_y[(size_t)b * H_ + hh];
        float yn = (y - g_mu[hh]) * g_rstd[hh] * gamma[hh] + beta[hh];
        s0 += yn * W2[hh];
        s1 += yn * W2[H_ + hh];
        s2 += yn * W2[2 * H_ + hh];
    }
#pragma unroll
    for (int o = 16; o; o >>= 1) {
        s0 += __shfl_xor_sync(0xffffffffu, s0, o);
        s1 += __shfl_xor_sync(0xffffffffu, s1, o);
        s2 += __shfl_xor_sync(0xffffffffu, s2, o);
    }
    if (lane == 0) { red[0][warp] = s0; red[1][warp] = s1; red[2][warp] = s2; }
    __syncthreads();
    if (tid < 3) {
        float t = 0.f;
#pragma unroll
        for (int w = 0; w < 8; w++) t += red[tid][w];
        out[b * 3 + tid] = t + b2[tid];
    }
}

// =====================================================================
// launcher
// =====================================================================
extern "C" void kernel_launch(void* const* d_in, const int* in_sizes, int n_in,
                              void* d_out, int out_size)
{
    const float* palette  = (const float*)d_in[0];
    const float* last_ctx = (const float*)d_in[1];
    const float* last_h   = (const float*)d_in[2];
    const float* enc      = (const float*)d_in[3];
    const int*   lens     = (const int*)d_in[4];
    const float* attn_W = (const float*)d_in[6];
    const float* attn_b = (const float*)d_in[7];
    const float* Wih    = (const float*)d_in[8];
    const float* Whh    = (const float*)d_in[9];
    const float* bih    = (const float*)d_in[10];
    const float* bhh    = (const float*)d_in[11];
    const float* W1     = (const float*)d_in[12];
    const float* b1     = (const float*)d_in[13];
    const float* gamma  = (const float*)d_in[14];
    const float* beta   = (const float*)d_in[15];
    const float* W2     = (const float*)d_in[16];
    const float* b2     = (const float*)d_in[17];

    float* out_main = (float*)d_out;
    float* out_ctx = 0;
    float* out_h = 0;
    float* out_w = 0;
    if (out_size >= B_ * 3 + 2 * B_ * H_ + B_ * S_) {
        out_ctx = out_main + B_ * 3;
        out_h   = out_ctx + B_ * H_;
        out_w   = out_h + B_ * H_;
    }

    __nv_bfloat16 *p_wih_hi, *p_wih_lo, *p_whh_hi, *p_whh_lo;
    __nv_bfloat16 *p_qw_hi, *p_qw_lo, *p_w1_hi, *p_w1_lo;
    cudaGetSymbolAddress((void**)&p_wih_hi, g_wih_hi);
    cudaGetSymbolAddress((void**)&p_wih_lo, g_wih_lo);
    cudaGetSymbolAddress((void**)&p_whh_hi, g_whh_hi);
    cudaGetSymbolAddress((void**)&p_whh_lo, g_whh_lo);
    cudaGetSymbolAddress((void**)&p_qw_hi,  g_qw_hi);
    cudaGetSymbolAddress((void**)&p_qw_lo,  g_qw_lo);
    cudaGetSymbolAddress((void**)&p_w1_hi,  g_w1_hi);
    cudaGetSymbolAddress((void**)&p_w1_lo,  g_w1_lo);

    // 0) pack weights (hi/lo bf16) and activations
    pack_w_kernel<<<3 * H_ * H_ / 256, 256>>>(Wih, H_ + P_, 3, p_wih_hi, p_wih_lo, 10);
    pack_w_kernel<<<3 * H_ * H_ / 256, 256>>>(Whh, H_, 0, p_whh_hi, p_whh_lo, 10);
    pack_w_kernel<<<H_ * H_ / 256, 256>>>(attn_W, H_, 0, p_qw_hi, p_qw_lo, 10);
    pack_w_kernel<<<H_ * 2 * H_ / 256, 256>>>(W1, 2 * H_, 0, p_w1_hi, p_w1_lo, 11);
    pack_act_kernel<<<B_ * H_ / 256, 256>>>(last_ctx, last_h);
    gp_kernel<<<3 * H_ / 256, 256>>>(palette, Wih);

    // 1) gi / gh tensor-core GEMMs (384 CTAs)
    gemm_dual<<<dim3(3 * H_ / 64, B_ / 64, 2), 128>>>();

    // 2) gates -> h (fp32 out + bf16 hi/lo)
    gru_gate_kernel<<<B_ * H_ / 256, 256>>>(last_h, bih, bhh, out_h);

    // 3) q partials (split-K 2, 128 CTAs)
    gemm_q<<<dim3(H_ / 64, B_ / 64, 2), 128>>>();

    // 4) attention
    attn_part_kernel<<<dim3(B_, 4), 256>>>(enc, lens, attn_b);
    attn_comb_kernel<<<B_, 256>>>(lens, out_ctx, out_w);

    // 5) y partials (split-K 2, 128 CTAs)
    gemm_y<<<dim3(H_ / 64, B_ / 64, 2), 128>>>();

    // 6) BN + final projection
    bn_reduce_stats<<<H_ / 256, 256>>>(b1);
    out_kernel<<<B_, 256>>>(gamma, beta, W2, b2, out_main);
}